// round 15
// baseline (speedup 1.0000x reference)
#include <cuda_runtime.h>
#include <cuda_bf16.h>
#include <math.h>

#define NW 20000
#define NE 30000
#define ER 200000
#define EE 200000
#define H 512
#define MDIM 512
#define ECH 4101
#define ECHP 4104
#define OUT_DIM 250
#define NLAYER 4
#define NREL 3
#define SLOPE 0.2f

#define WCAT 2048   // [hw | agg0 | agg1 | agg2]
#define ECAT 1024   // [he | agge]

// ---------------- scratch (device globals; no runtime allocation) ----------------
__device__ float g_wcatA[(size_t)NW * WCAT];
__device__ float g_wcatB[(size_t)NW * WCAT];
__device__ float g_ecatA[(size_t)NE * ECAT];
__device__ float g_ecatB[(size_t)NE * ECAT];
__device__ __nv_bfloat16 g_hwbf[(size_t)NW * H];
__device__ __nv_bfloat16 g_hebf[(size_t)NE * H];
__device__ float g_xpad[(size_t)NE * ECHP];
__device__ float g_wpad[(size_t)ECHP * H];
__device__ float g_tmp[(size_t)NE * H];
__device__ float g_tmp2[(size_t)NW * H];
__device__ float g_Bw[(size_t)WCAT * H];
__device__ float g_Be[(size_t)ECAT * H];
__device__ float g_lpad[(size_t)H * 256];
__device__ float g_s[NW];
__device__ float g_stat[2];
__device__ float g_vec[4 * H];
// CSR structures
__device__ int g_cnt4[3 * NW + NE];
__device__ int g_cur4[3 * NW + NE];
__device__ int g_offw[NREL * (NW + 1)];
__device__ int g_offe[NE + 1];
__device__ int g_psrcw[NREL * ER];
__device__ int g_pijw[NREL * ER];
__device__ int g_psrce[EE];

__device__ __forceinline__ float leakyf(float v) { return v > 0.f ? v : SLOPE * v; }

__device__ __forceinline__ float rna(float f) {
    unsigned u;
    asm("cvt.rna.tf32.f32 %0, %1;" : "=r"(u) : "f"(f));
    return __uint_as_float(u);
}

// ===== TF32 tensor-core GEMM body (cp.async 2-stage, BKT=32, ldmatrix A) =====
#define BM 128
#define BN 128
#define BKT 32
#define ASTRIDE 36
#define BSTRIDE 132
#define STAGES 2
#define GEMM_SMEM ((STAGES * BM * ASTRIDE + STAGES * BKT * BSTRIDE) * 4)

struct GP {
    const float* A; const float* B; float* C;
    int M, N, K, lda, ldc, nstore;
    const float* bias; float scale; int leaky, rnd;
    __nv_bfloat16* bfOut;
};

__device__ __forceinline__ void cp16(unsigned dst, const float* src, int sz) {
    asm volatile("cp.async.ca.shared.global [%0], [%1], 16, %2;\n"
                 :: "r"(dst), "l"(src), "r"(sz));
}

__device__ __forceinline__ void gemm_body(const GP p, int bx, int by, float* smemBuf)
{
    float (*Bs)[BKT][BSTRIDE] = (float (*)[BKT][BSTRIDE])(smemBuf + STAGES * BM * ASTRIDE);
    unsigned aSm = (unsigned)__cvta_generic_to_shared(smemBuf);
    unsigned bBase = aSm + STAGES * BM * ASTRIDE * 4;

    const int tid  = threadIdx.x;
    const int lane = tid & 31;
    const int warp = tid >> 5;
    const int wm = warp & 1;
    const int wn = warp >> 1;
    const int grp = lane >> 2;
    const int tig = lane & 3;

    const int rowBase = by * BM;
    const int colBase = bx * BN;
    const int ntiles = (p.K + BKT - 1) / BKT;

    const int lmOff = (lane & 15) * ASTRIDE + ((lane >> 4) & 1) * 4;

    float acc[4][4][4];
    #pragma unroll
    for (int i = 0; i < 4; i++)
        #pragma unroll
        for (int j = 0; j < 4; j++)
            #pragma unroll
            for (int q = 0; q < 4; q++) acc[i][j][q] = 0.f;

    auto issue = [&](int stage, int t) {
        int k0 = t * BKT;
        #pragma unroll
        for (int i = 0; i < 4; i++) {
            int v = tid + i * 256;
            int r = v >> 3, c = (v & 7) * 4;
            int gr = rowBase + r, gc = k0 + c;
            unsigned dst = aSm + (unsigned)(stage * BM * ASTRIDE + r * ASTRIDE + c) * 4;
            cp16(dst, p.A + (size_t)gr * p.lda + gc, (gr < p.M && gc < p.K) ? 16 : 0);
        }
        #pragma unroll
        for (int i = 0; i < 4; i++) {
            int v = tid + i * 256;
            int r = v >> 5, c = (v & 31) * 4;
            int gr = k0 + r, gc = colBase + c;
            unsigned dst = bBase + (unsigned)(stage * BKT * BSTRIDE + r * BSTRIDE + c) * 4;
            cp16(dst, p.B + (size_t)gr * p.N + gc, (gr < p.K && gc < p.N) ? 16 : 0);
        }
    };

    issue(0, 0);
    asm volatile("cp.async.commit_group;\n");

    for (int t = 0; t < ntiles; t++) {
        asm volatile("cp.async.wait_group 0;\n");
        __syncthreads();
        if (t + 1 < ntiles) issue((t + 1) & 1, t + 1);
        asm volatile("cp.async.commit_group;\n");
        int b = t & 1;
        const unsigned aStage = aSm + (unsigned)(b * BM * ASTRIDE) * 4;
        #pragma unroll
        for (int kk = 0; kk < BKT; kk += 8) {
            unsigned bf[4][2];
            #pragma unroll
            for (int nt = 0; nt < 4; nt++) {
                int n = wn * 32 + nt * 8 + grp;
                bf[nt][0] = __float_as_uint(Bs[b][kk + tig][n]);
                bf[nt][1] = __float_as_uint(Bs[b][kk + tig + 4][n]);
            }
            #pragma unroll
            for (int mt = 0; mt < 4; mt++) {
                unsigned aAddr = aStage +
                    (unsigned)(((wm * 64 + mt * 16) * ASTRIDE) + kk + lmOff) * 4;
                unsigned a0, a1, a2, a3;
                asm volatile(
                    "ldmatrix.sync.aligned.m8n8.x4.shared.b16 {%0,%1,%2,%3}, [%4];"
                    : "=r"(a0), "=r"(a1), "=r"(a2), "=r"(a3) : "r"(aAddr));
                #pragma unroll
                for (int nt = 0; nt < 4; nt++) {
                    asm volatile(
                        "mma.sync.aligned.m16n8k8.row.col.f32.tf32.tf32.f32 "
                        "{%0,%1,%2,%3}, {%4,%5,%6,%7}, {%8,%9}, {%0,%1,%2,%3};\n"
                        : "+f"(acc[mt][nt][0]), "+f"(acc[mt][nt][1]),
                          "+f"(acc[mt][nt][2]), "+f"(acc[mt][nt][3])
                        : "r"(a0), "r"(a1), "r"(a2), "r"(a3),
                          "r"(bf[nt][0]), "r"(bf[nt][1]));
                }
            }
        }
    }

    #pragma unroll
    for (int mt = 0; mt < 4; mt++) {
        #pragma unroll
        for (int nt = 0; nt < 4; nt++) {
            int r0 = rowBase + wm * 64 + mt * 16 + grp;
            int c0 = colBase + wn * 32 + nt * 8 + tig * 2;
            #pragma unroll
            for (int half = 0; half < 2; half++) {
                int r = r0 + half * 8;
                if (r >= p.M) continue;
                #pragma unroll
                for (int j = 0; j < 2; j++) {
                    int c = c0 + j;
                    if (c >= p.nstore) continue;
                    float v = acc[mt][nt][half * 2 + j];
                    if (p.bias) v += p.bias[c];
                    v *= p.scale;
                    if (p.leaky) v = leakyf(v);
                    if (p.rnd) v = rna(v);
                    p.C[(size_t)r * p.ldc + c] = v;
                    if (p.bfOut) p.bfOut[(size_t)r * H + c] = __float2bfloat16_rn(v);
                }
            }
        }
    }
}

__global__ __launch_bounds__(256, 2)
void mma_gemm_single(GP p)
{
    extern __shared__ float smemBuf[];
    gemm_body(p, blockIdx.x, blockIdx.y, smemBuf);
}

__global__ __launch_bounds__(256, 2)
void mma_gemm_dual(GP p0, GP p1, int gx0, int n0, int gx1)
{
    extern __shared__ float smemBuf[];
    int bid = blockIdx.x;
    if (bid < n0) gemm_body(p0, bid % gx0, bid / gx0, smemBuf);
    else {
        bid -= n0;
        gemm_body(p1, bid % gx1, bid / gx1, smemBuf);
    }
}

// ---------------------------- CSR build kernels ----------------------------
__global__ void hist_kernel(const int* __restrict__ dst, int* __restrict__ cnt, int n)
{
    int e = blockIdx.x * 256 + threadIdx.x;
    if (e < n) atomicAdd(&cnt[dst[e]], 1);
}

__global__ __launch_bounds__(1024)
void scan4_kernel(const int* __restrict__ cntAll, int* __restrict__ offw,
                  int* __restrict__ offe)
{
    int b = blockIdx.x;
    const int* cnt;
    int* off;
    int n;
    if (b < 3) { cnt = cntAll + b * NW; off = offw + b * (NW + 1); n = NW; }
    else       { cnt = cntAll + 3 * NW; off = offe; n = NE; }
    __shared__ int sm[1024];
    __shared__ int carry;
    if (threadIdx.x == 0) carry = 0;
    __syncthreads();
    for (int base = 0; base < n; base += 1024) {
        int i = base + threadIdx.x;
        int v = (i < n) ? cnt[i] : 0;
        sm[threadIdx.x] = v;
        __syncthreads();
        for (int o = 1; o < 1024; o <<= 1) {
            int t = (threadIdx.x >= o) ? sm[threadIdx.x - o] : 0;
            __syncthreads();
            sm[threadIdx.x] += t;
            __syncthreads();
        }
        if (i < n) off[i] = carry + sm[threadIdx.x] - v;
        __syncthreads();
        if (threadIdx.x == 1023) carry += sm[1023];
        __syncthreads();
    }
    if (threadIdx.x == 0) off[n] = carry;
}

__global__ void place_kernel(const int* __restrict__ src, const int* __restrict__ dst,
                             const int* __restrict__ ij, const int* __restrict__ off,
                             int* __restrict__ cur, int* __restrict__ psrc,
                             int* __restrict__ pij, int n)
{
    int e = blockIdx.x * 256 + threadIdx.x;
    if (e >= n) return;
    int d = dst[e];
    int p = off[d] + atomicAdd(&cur[d], 1);
    psrc[p] = src[e];
    if (pij) pij[p] = ij[e];
}

// ---------------------------- aggregation kernels (bf16 gathers) ----------------
__global__ __launch_bounds__(128)
void agg_win_kernel(const int* __restrict__ offw, const int* __restrict__ psrcw,
                    const int* __restrict__ pijw,
                    const __nv_bfloat16* __restrict__ hwbf,
                    const __nv_bfloat16* __restrict__ hebf,
                    float* __restrict__ wOut)
{
    int r = blockIdx.y;
    const int* off  = offw + r * (NW + 1);
    const int* psrc = psrcw + (size_t)r * ER;
    const int* pij  = pijw + (size_t)r * ER;
    int d = blockIdx.x;
    int s0 = off[d], s1 = off[d + 1];
    int c = threadIdx.x;
    float4 acc = make_float4(0.f, 0.f, 0.f, 0.f);
    for (int k = s0; k < s1; k++) {
        uint2 aw = *(const uint2*)(hwbf + (size_t)psrc[k] * H + (c << 2));
        uint2 ae = *(const uint2*)(hebf + (size_t)pij[k] * H + (c << 2));
        float2 w0 = __bfloat1622float2(*reinterpret_cast<__nv_bfloat162*>(&aw.x));
        float2 w1 = __bfloat1622float2(*reinterpret_cast<__nv_bfloat162*>(&aw.y));
        float2 e0 = __bfloat1622float2(*reinterpret_cast<__nv_bfloat162*>(&ae.x));
        float2 e1 = __bfloat1622float2(*reinterpret_cast<__nv_bfloat162*>(&ae.y));
        acc.x += w0.x + e0.x; acc.y += w0.y + e0.y;
        acc.z += w1.x + e1.x; acc.w += w1.y + e1.y;
    }
    float rc = 1.f / fmaxf((float)(s1 - s0), 1.f);
    float4 o = make_float4(rna(acc.x * rc), rna(acc.y * rc),
                           rna(acc.z * rc), rna(acc.w * rc));
    *(float4*)(wOut + (size_t)d * WCAT + (size_t)(1 + r) * H + (c << 2)) = o;
}

__global__ __launch_bounds__(128)
void agg_edge_kernel(const int* __restrict__ off, const int* __restrict__ psrc,
                     const __nv_bfloat16* __restrict__ hebf, float* __restrict__ outBase)
{
    int d = blockIdx.x;
    int s0 = off[d], s1 = off[d + 1];
    int c = threadIdx.x;
    float4 acc = make_float4(0.f, 0.f, 0.f, 0.f);
    for (int k = s0; k < s1; k++) {
        uint2 ae = *(const uint2*)(hebf + (size_t)psrc[k] * H + (c << 2));
        float2 e0 = __bfloat1622float2(*reinterpret_cast<__nv_bfloat162*>(&ae.x));
        float2 e1 = __bfloat1622float2(*reinterpret_cast<__nv_bfloat162*>(&ae.y));
        acc.x += e0.x; acc.y += e0.y; acc.z += e1.x; acc.w += e1.y;
    }
    float rc = 1.f / fmaxf((float)(s1 - s0), 1.f);
    float4 o = make_float4(rna(acc.x * rc), rna(acc.y * rc),
                           rna(acc.z * rc), rna(acc.w * rc));
    *(float4*)(outBase + (size_t)d * ECAT + (c << 2)) = o;
}

// ---------------------------- fused pooling kernels ----------------------------
__global__ __launch_bounds__(512)
void pool_head_kernel(const float* __restrict__ S, const float* __restrict__ Wq,
                      const float* __restrict__ Wk, const float* __restrict__ W1,
                      float* __restrict__ wfin_out)
{
    __shared__ float sS[H], sq[H], swk[H];
    int tid = threadIdx.x;
    sS[tid] = S[tid];
    __syncthreads();
    float acc = 0.f;
    for (int k = 0; k < H; k++) acc += sS[k] * Wq[(size_t)k * H + tid];
    sq[tid] = acc;
    __syncthreads();
    int warp = tid >> 5, lane = tid & 31;
    for (int row = warp; row < H; row += 16) {
        float a = 0.f;
        for (int j = lane; j < H; j += 32) a += Wk[(size_t)row * H + j] * sq[j];
        #pragma unroll
        for (int o = 16; o > 0; o >>= 1) a += __shfl_down_sync(0xffffffffu, a, o);
        if (!lane) swk[row] = a;
    }
    __syncthreads();
    for (int row = warp; row < H; row += 16) {
        float a = 0.f;
        for (int j = lane; j < H; j += 32) a += W1[(size_t)row * H + j] * swk[j];
        #pragma unroll
        for (int o = 16; o > 0; o >>= 1) a += __shfl_down_sync(0xffffffffu, a, o);
        if (!lane) wfin_out[row] = a;
    }
}

__global__ void scores_kernel(const __nv_bfloat16* __restrict__ hwbf,
                              const float* __restrict__ w, float* __restrict__ s,
                              float scale)
{
    int row = (blockIdx.x * blockDim.x + threadIdx.x) >> 5;
    int lane = threadIdx.x & 31;
    if (row >= NW) return;
    const __nv_bfloat16* p = hwbf + (size_t)row * H;
    float acc = 0.f;
    for (int c = lane; c < H; c += 32) acc += __bfloat162float(p[c]) * w[c];
    #pragma unroll
    for (int o = 16; o > 0; o >>= 1) acc += __shfl_down_sync(0xffffffffu, acc, o);
    if (!lane) s[row] = acc * scale;
}

__global__ __launch_bounds__(1024)
void softmax1b_kernel(float* __restrict__ s, int n, float* __restrict__ stat)
{
    __shared__ float red[32];
    int tid = threadIdx.x;
    float m = -3.4e38f;
    for (int i = tid; i < n; i += 1024) m = fmaxf(m, s[i]);
    #pragma unroll
    for (int o = 16; o > 0; o >>= 1) m = fmaxf(m, __shfl_down_sync(0xffffffffu, m, o));
    if ((tid & 31) == 0) red[tid >> 5] = m;
    __syncthreads();
    if (tid < 32) {
        float v = red[tid];
        #pragma unroll
        for (int o = 16; o > 0; o >>= 1) v = fmaxf(v, __shfl_down_sync(0xffffffffu, v, o));
        if (!tid) red[0] = v;
    }
    __syncthreads();
    float mx = red[0];
    __syncthreads();
    float sum = 0.f;
    for (int i = tid; i < n; i += 1024) {
        float e = expf(s[i] - mx);
        s[i] = e;
        sum += e;
    }
    #pragma unroll
    for (int o = 16; o > 0; o >>= 1) sum += __shfl_down_sync(0xffffffffu, sum, o);
    if ((tid & 31) == 0) red[tid >> 5] = sum;
    __syncthreads();
    if (tid < 32) {
        float v = red[tid];
        #pragma unroll
        for (int o = 16; o > 0; o >>= 1) v += __shfl_down_sync(0xffffffffu, v, o);
        if (!tid) { stat[0] = mx; stat[1] = v; }
    }
}

__global__ void attnv_kernel(const __nv_bfloat16* __restrict__ hwbf,
                             const float* __restrict__ w, const float* __restrict__ sum,
                             float* __restrict__ out, int n)
{
    int c = blockIdx.x * 256 + threadIdx.x;
    int chunk = (n + gridDim.y - 1) / gridDim.y;
    int r0 = blockIdx.y * chunk;
    int r1 = min(r0 + chunk, n);
    float acc = 0.f;
    for (int r = r0; r < r1; r++)
        acc += w[r] * __bfloat162float(hwbf[(size_t)r * H + c]);
    atomicAdd(&out[c], acc / sum[0]);
}

__global__ __launch_bounds__(512)
void pool_tail_kernel(const float* __restrict__ u, const float* __restrict__ W1,
                      const float* __restrict__ b1, const float* __restrict__ Wv,
                      const float* __restrict__ W2, const float* __restrict__ b2,
                      const float* __restrict__ Wg, const float* __restrict__ cb,
                      float* __restrict__ bs2)
{
    __shared__ float s0[H], s1[H], s2[H];
    int tid = threadIdx.x;
    s0[tid] = u[tid];
    __syncthreads();
    float acc = b1[tid];
    for (int k = 0; k < H; k++) acc += s0[k] * W1[(size_t)k * H + tid];
    s1[tid] = acc;
    __syncthreads();
    acc = 0.f;
    for (int k = 0; k < H; k++) acc += s1[k] * Wv[(size_t)k * H + tid];
    s2[tid] = acc;
    __syncthreads();
    acc = b2[tid];
    for (int k = 0; k < H; k++) acc += s2[k] * W2[(size_t)k * H + tid];
    s0[tid] = acc;
    __syncthreads();
    acc = 0.f;
    const float* Wg1 = Wg + (size_t)H * H;
    const float* Wg2 = Wg + 2 * (size_t)H * H;
    for (int k = 0; k < H; k++) {
        size_t o = (size_t)k * H + tid;
        acc += s0[k] * (Wg[o] + Wg1[o] + Wg2[o]);
    }
    bs2[tid] = acc + cb[tid] + cb[H + tid] + cb[2 * H + tid];
}

// ---------------------------- small kernels ----------------------------
__global__ void padx_kernel(const float* __restrict__ x, float* __restrict__ xp)
{
    size_t idx = (size_t)blockIdx.x * blockDim.x + threadIdx.x;
    if (idx >= (size_t)NE * ECHP) return;
    int r = (int)(idx / ECHP), c = (int)(idx % ECHP);
    xp[idx] = (c < ECH) ? rna(x[(size_t)r * ECH + c]) : 0.f;
}

__global__ void padw_kernel(const float* __restrict__ w, float* __restrict__ wp)
{
    size_t idx = (size_t)blockIdx.x * blockDim.x + threadIdx.x;
    if (idx >= (size_t)ECHP * H) return;
    int r = (int)(idx / H);
    wp[idx] = (r < ECH) ? rna(w[idx]) : 0.f;
}

__global__ void padlin_kernel(const float* __restrict__ w, float* __restrict__ wp)
{
    int idx = blockIdx.x * 256 + threadIdx.x;
    if (idx >= H * 256) return;
    int r = idx >> 8, c = idx & 255;
    wp[idx] = (c < OUT_DIM) ? rna(w[r * OUT_DIM + c]) : 0.f;
}

__global__ void rcopy_kernel(const float* __restrict__ in, float* __restrict__ out, size_t n)
{
    size_t idx = (size_t)blockIdx.x * blockDim.x + threadIdx.x;
    if (idx < n) out[idx] = rna(in[idx]);
}

__global__ void build_bw_kernel(const float* __restrict__ Wl, const float* __restrict__ Wr,
                                float* __restrict__ out)
{
    size_t idx = (size_t)blockIdx.x * blockDim.x + threadIdx.x;
    if (idx >= (size_t)WCAT * H) return;
    int row = (int)(idx / H), j = (int)(idx % H);
    float v;
    if (row < H) {
        v = Wr[(size_t)row * H + j] + Wr[(size_t)(H + row) * H + j]
          + Wr[(size_t)(2 * H + row) * H + j];
    } else {
        v = Wl[(size_t)(row - H) * H + j];
    }
    out[idx] = rna(v);
}

__global__ void build_be_kernel(const float* __restrict__ Wl, const float* __restrict__ Wr,
                                float* __restrict__ out)
{
    size_t idx = (size_t)blockIdx.x * blockDim.x + threadIdx.x;
    if (idx >= (size_t)ECAT * H) return;
    int row = (int)(idx / H), j = (int)(idx % H);
    out[idx] = rna((row < H) ? Wr[(size_t)row * H + j] : Wl[(size_t)(row - H) * H + j]);
}

// ------------------------------- host orchestration -------------------------------
static GP mkGP(const float* A, const float* B, float* C, int M, int N, int K,
               int lda, int ldc, int nstore, const float* bias, float scale,
               int leaky, int rnd, __nv_bfloat16* bfOut)
{
    GP p; p.A = A; p.B = B; p.C = C; p.M = M; p.N = N; p.K = K;
    p.lda = lda; p.ldc = ldc; p.nstore = nstore; p.bias = bias;
    p.scale = scale; p.leaky = leaky; p.rnd = rnd; p.bfOut = bfOut;
    return p;
}

static void gemmSingle(const GP& p)
{
    dim3 grid((p.N + BN - 1) / BN, (p.M + BM - 1) / BM);
    mma_gemm_single<<<grid, 256, GEMM_SMEM>>>(p);
}

static void gemmDual(const GP& a, const GP& b)
{
    int gxa = (a.N + BN - 1) / BN, gya = (a.M + BM - 1) / BM;
    int gxb = (b.N + BN - 1) / BN, gyb = (b.M + BM - 1) / BM;
    int n0 = gxa * gya;
    mma_gemm_dual<<<n0 + gxb * gyb, 256, GEMM_SMEM>>>(a, b, gxa, n0, gxb);
}

extern "C" void kernel_launch(void* const* d_in, const int* in_sizes, int n_in,
                              void* d_out, int out_size)
{
    const float* x_win       = (const float*)d_in[0];
    const float* x_edge      = (const float*)d_in[1];
    const float* W_pre_win   = (const float*)d_in[2];
    const float* W_post_win  = (const float*)d_in[3];
    const float* W_pre_edge  = (const float*)d_in[4];
    const float* W_post_edge = (const float*)d_in[5];
    const float* conv_Wl     = (const float*)d_in[6];
    const float* conv_Wr     = (const float*)d_in[7];
    const float* conv_Wg     = (const float*)d_in[8];
    const float* conv_b      = (const float*)d_in[9];
    const float* econv_Wl    = (const float*)d_in[10];
    const float* econv_Wr    = (const float*)d_in[11];
    const float* econv_b     = (const float*)d_in[12];
    const float* pool_lin1_W = (const float*)d_in[13];
    const float* pool_lin1_b = (const float*)d_in[14];
    const float* pool_S      = (const float*)d_in[15];
    const float* pool_Wq     = (const float*)d_in[16];
    const float* pool_Wk     = (const float*)d_in[17];
    const float* pool_Wv     = (const float*)d_in[18];
    const float* pool_lin2_W = (const float*)d_in[19];
    const float* pool_lin2_b = (const float*)d_in[20];
    const float* lin_W       = (const float*)d_in[21];
    const float* lin_b       = (const float*)d_in[22];
    const int* ein = (const int*)d_in[23];
    const int* eic = (const int*)d_in[24];
    const int* eis = (const int*)d_in[25];
    const int* ijn = (const int*)d_in[26];
    const int* ijc = (const int*)d_in[27];
    const int* ijs = (const int*)d_in[28];
    const int* eee = (const int*)d_in[29];

    static int inited = 0;
    static cudaStream_t s2;
    static cudaEvent_t evFork, evCSR, evTop[NLAYER], evPool[NLAYER];
    if (!inited) {
        cudaFuncSetAttribute(mma_gemm_single, cudaFuncAttributeMaxDynamicSharedMemorySize,
                             GEMM_SMEM);
        cudaFuncSetAttribute(mma_gemm_dual, cudaFuncAttributeMaxDynamicSharedMemorySize,
                             GEMM_SMEM);
        cudaStreamCreateWithFlags(&s2, cudaStreamNonBlocking);
        cudaEventCreateWithFlags(&evFork, cudaEventDisableTiming);
        cudaEventCreateWithFlags(&evCSR, cudaEventDisableTiming);
        for (int i = 0; i < NLAYER; i++) {
            cudaEventCreateWithFlags(&evTop[i], cudaEventDisableTiming);
            cudaEventCreateWithFlags(&evPool[i], cudaEventDisableTiming);
        }
        inited = 1;
    }

    float *wcatA, *wcatB, *ecatA, *ecatB, *xpad, *wpad, *tmp, *tmp2, *Bw, *Be, *lpad;
    float *sbuf, *stat, *vec;
    __nv_bfloat16 *hwbf, *hebf;
    int *cnt4, *cur4, *offw, *offe, *psrcw, *pijw, *psrce;
    cudaGetSymbolAddress((void**)&wcatA, g_wcatA);
    cudaGetSymbolAddress((void**)&wcatB, g_wcatB);
    cudaGetSymbolAddress((void**)&ecatA, g_ecatA);
    cudaGetSymbolAddress((void**)&ecatB, g_ecatB);
    cudaGetSymbolAddress((void**)&hwbf,  g_hwbf);
    cudaGetSymbolAddress((void**)&hebf,  g_hebf);
    cudaGetSymbolAddress((void**)&xpad,  g_xpad);
    cudaGetSymbolAddress((void**)&wpad,  g_wpad);
    cudaGetSymbolAddress((void**)&tmp,   g_tmp);
    cudaGetSymbolAddress((void**)&tmp2,  g_tmp2);
    cudaGetSymbolAddress((void**)&Bw,    g_Bw);
    cudaGetSymbolAddress((void**)&Be,    g_Be);
    cudaGetSymbolAddress((void**)&lpad,  g_lpad);
    cudaGetSymbolAddress((void**)&sbuf,  g_s);
    cudaGetSymbolAddress((void**)&stat,  g_stat);
    cudaGetSymbolAddress((void**)&vec,   g_vec);
    cudaGetSymbolAddress((void**)&cnt4,  g_cnt4);
    cudaGetSymbolAddress((void**)&cur4,  g_cur4);
    cudaGetSymbolAddress((void**)&offw,  g_offw);
    cudaGetSymbolAddress((void**)&offe,  g_offe);
    cudaGetSymbolAddress((void**)&psrcw, g_psrcw);
    cudaGetSymbolAddress((void**)&pijw,  g_pijw);
    cudaGetSymbolAddress((void**)&psrce, g_psrce);

    float* wfin = vec;
    float* u    = vec + H;
    float* bs2  = vec + 2 * H;

    const int* srcs[NREL] = {ein, eic, eis};
    const int* ijx[NREL]  = {ijn, ijc, ijs};

    // ================= fork: CSR build on s2, concurrent with pretransforms ======
    cudaEventRecord(evFork, 0);
    cudaStreamWaitEvent(s2, evFork, 0);

    cudaMemsetAsync(cnt4, 0, (3 * NW + NE) * sizeof(int), s2);
    cudaMemsetAsync(cur4, 0, (3 * NW + NE) * sizeof(int), s2);
    for (int r = 0; r < NREL; r++)
        hist_kernel<<<(ER + 255) / 256, 256, 0, s2>>>(srcs[r] + ER, cnt4 + r * NW, ER);
    hist_kernel<<<(EE + 255) / 256, 256, 0, s2>>>(eee + EE, cnt4 + 3 * NW, EE);
    scan4_kernel<<<4, 1024, 0, s2>>>(cnt4, offw, offe);
    for (int r = 0; r < NREL; r++)
        place_kernel<<<(ER + 255) / 256, 256, 0, s2>>>(srcs[r], srcs[r] + ER, ijx[r],
                                                       offw + r * (NW + 1), cur4 + r * NW,
                                                       psrcw + (size_t)r * ER,
                                                       pijw + (size_t)r * ER, ER);
    place_kernel<<<(EE + 255) / 256, 256, 0, s2>>>(eee, eee + EE, nullptr, offe,
                                                   cur4 + 3 * NW, psrce, nullptr, EE);
    cudaEventRecord(evCSR, s2);

    // ---- main: rounded operand staging + pretransforms ----
    padx_kernel<<<(int)(((size_t)NE * ECHP + 255) / 256), 256>>>(x_edge, xpad);
    padw_kernel<<<(int)(((size_t)ECHP * H + 255) / 256), 256>>>(W_pre_edge, wpad);
    rcopy_kernel<<<(int)(((size_t)NW * MDIM + 255) / 256), 256>>>(
        x_win, wcatB, (size_t)NW * MDIM);
    rcopy_kernel<<<(H * H + 255) / 256, 256>>>(W_pre_win, Bw, (size_t)H * H);
    rcopy_kernel<<<(H * H + 255) / 256, 256>>>(W_post_win, Bw + (size_t)H * H, (size_t)H * H);
    rcopy_kernel<<<(H * H + 255) / 256, 256>>>(W_post_edge, Be, (size_t)H * H);

    gemmDual(mkGP(wcatB, Bw, tmp2, NW, H, MDIM, MDIM, H, H, nullptr, 1.f, 1, 1, nullptr),
             mkGP(xpad, wpad, tmp, NE, H, ECHP, ECHP, H, H, nullptr, 1.f, 1, 1, nullptr));
    gemmDual(mkGP(tmp2, Bw + (size_t)H * H, wcatA, NW, H, H, H, WCAT, H,
                  nullptr, 1.f, 1, 1, hwbf),
             mkGP(tmp, Be, ecatA, NE, H, H, H, ECAT, H, nullptr, 1.f, 1, 1, hebf));

    cudaStreamWaitEvent(0, evCSR, 0);   // CSR needed by first agg_win

    float* wA = wcatA; float* wB = wcatB;
    float* eA = ecatA; float* eB = ecatB;
    const float scale = 1.f / sqrtf((float)H);

    for (int l = 0; l < NLAYER; l++) {
        size_t wOff = (size_t)l * H * H;
        size_t wb   = (size_t)l * NREL * H * H;
        size_t bb   = (size_t)l * NREL * H;

        // fork: pooling + weight builds on s2 (reads hwbf + const weights only)
        cudaEventRecord(evTop[l], 0);
        cudaStreamWaitEvent(s2, evTop[l], 0);
        pool_head_kernel<<<1, 512, 0, s2>>>(pool_S + (size_t)l * H, pool_Wq + wOff,
                                            pool_Wk + wOff, pool_lin1_W + wOff, wfin);
        scores_kernel<<<(NW * 32 + 255) / 256, 256, 0, s2>>>(hwbf, wfin, sbuf, scale);
        softmax1b_kernel<<<1, 1024, 0, s2>>>(sbuf, NW, stat);
        cudaMemsetAsync(u, 0, H * sizeof(float), s2);
        {
            dim3 ag(H / 256, 79);
            attnv_kernel<<<ag, 256, 0, s2>>>(hwbf, sbuf, stat + 1, u, NW);
        }
        pool_tail_kernel<<<1, 512, 0, s2>>>(u, pool_lin1_W + wOff,
                                            pool_lin1_b + (size_t)l * H,
                                            pool_Wv + wOff, pool_lin2_W + wOff,
                                            pool_lin2_b + (size_t)l * H,
                                            conv_Wg + wb, conv_b + bb, bs2);
        build_bw_kernel<<<(int)(((size_t)WCAT * H + 255) / 256), 256, 0, s2>>>(
            conv_Wl + wb, conv_Wr + wb, Bw);
        if (l < NLAYER - 1)
            build_be_kernel<<<(int)(((size_t)ECAT * H + 255) / 256), 256, 0, s2>>>(
                econv_Wl + wOff, econv_Wr + wOff, Be);
        cudaEventRecord(evPool[l], s2);

        // main: CSR aggregations (independent of pooling)
        {
            dim3 ag(NW, NREL);
            agg_win_kernel<<<ag, 128>>>(offw, psrcw, pijw, hwbf, hebf, wA);
        }
        if (l < NLAYER - 1)
            agg_edge_kernel<<<NE, 128>>>(offe, psrce, hebf, eA + H);

        // join: conv GEMMs need bs2/Bw/Be from s2
        cudaStreamWaitEvent(0, evPool[l], 0);
        GP wp = mkGP(wA, Bw, wB, NW, H, WCAT, WCAT, WCAT, H,
                     bs2, 1.f / (float)NREL, 1, 1, hwbf);
        if (l < NLAYER - 1) {
            GP ep = mkGP(eA, Be, eB, NE, H, ECAT, ECAT, ECAT, H,
                         econv_b + (size_t)l * H, 1.f, 1, 1, hebf);
            gemmDual(wp, ep);
        } else {
            gemmSingle(wp);
        }

        float* t = wA; wA = wB; wB = t;
        t = eA; eA = eB; eB = t;
    }

    // ---- final linear on the aligned path (lin_W padded into lpad) ----
    padlin_kernel<<<(H * 256 + 255) / 256, 256>>>(lin_W, lpad);
    gemmSingle(mkGP(wA, lpad, (float*)d_out, NW, 256, H, WCAT, OUT_DIM, OUT_DIM,
                    lin_b, 1.f, 0, 0, nullptr));
}

// round 17
// speedup vs baseline: 1.4225x; 1.4225x over previous
#include <cuda_runtime.h>
#include <cuda_bf16.h>
#include <math.h>

#define NW 20000
#define NE 30000
#define ER 200000
#define EE 200000
#define H 512
#define MDIM 512
#define ECH 4101
#define ECHP 4104
#define OUT_DIM 250
#define NLAYER 4
#define NREL 3
#define SLOPE 0.2f

#define WCAT 2048   // [hw | agg0 | agg1 | agg2]
#define ECAT 1024   // [he | agge]

// ---------------- scratch (device globals; no runtime allocation) ----------------
__device__ float g_wcatA[(size_t)NW * WCAT];
__device__ float g_wcatB[(size_t)NW * WCAT];
__device__ float g_ecatA[(size_t)NE * ECAT];
__device__ float g_ecatB[(size_t)NE * ECAT];
__device__ __nv_bfloat16 g_hwbf[(size_t)NW * H];
__device__ __nv_bfloat16 g_hebf[(size_t)NE * H];
__device__ float g_xpad[(size_t)NE * ECHP];
__device__ float g_wpad[(size_t)ECHP * H];
__device__ float g_tmp[(size_t)NE * H];
__device__ float g_tmp2[(size_t)NW * H];
__device__ float g_Bw[(size_t)WCAT * H];
__device__ float g_Be[(size_t)ECAT * H];
__device__ float g_lpad[(size_t)H * 256];
__device__ float g_s[NW];
__device__ float g_stat[2];
__device__ float g_wfin[NLAYER * H];
__device__ float g_vec[4 * H];
// CSR structures
__device__ int g_cnt4[3 * NW + NE];
__device__ int g_cur4[3 * NW + NE];
__device__ int g_offw[NREL * (NW + 1)];
__device__ int g_offe[NE + 1];
__device__ int g_psrcw[NREL * ER];
__device__ int g_pijw[NREL * ER];
__device__ int g_psrce[EE];

__device__ __forceinline__ float leakyf(float v) { return v > 0.f ? v : SLOPE * v; }

__device__ __forceinline__ float rna(float f) {
    unsigned u;
    asm("cvt.rna.tf32.f32 %0, %1;" : "=r"(u) : "f"(f));
    return __uint_as_float(u);
}

// ===== TF32 tensor-core GEMM body (cp.async 2-stage, BKT=32, ldmatrix A) =====
#define BM 128
#define BN 128
#define BKT 32
#define ASTRIDE 36
#define BSTRIDE 132
#define STAGES 2
#define GEMM_SMEM ((STAGES * BM * ASTRIDE + STAGES * BKT * BSTRIDE) * 4)

struct GP {
    const float* A; const float* B; float* C;
    int M, N, K, lda, ldc, nstore;
    const float* bias; float scale; int leaky, rnd;
    __nv_bfloat16* bfOut;
};

__device__ __forceinline__ void cp16(unsigned dst, const float* src, int sz) {
    asm volatile("cp.async.ca.shared.global [%0], [%1], 16, %2;\n"
                 :: "r"(dst), "l"(src), "r"(sz));
}

__device__ __forceinline__ void gemm_body(const GP p, int bx, int by, float* smemBuf)
{
    float (*Bs)[BKT][BSTRIDE] = (float (*)[BKT][BSTRIDE])(smemBuf + STAGES * BM * ASTRIDE);
    unsigned aSm = (unsigned)__cvta_generic_to_shared(smemBuf);
    unsigned bBase = aSm + STAGES * BM * ASTRIDE * 4;

    const int tid  = threadIdx.x;
    const int lane = tid & 31;
    const int warp = tid >> 5;
    const int wm = warp & 1;
    const int wn = warp >> 1;
    const int grp = lane >> 2;
    const int tig = lane & 3;

    const int rowBase = by * BM;
    const int colBase = bx * BN;
    const int ntiles = (p.K + BKT - 1) / BKT;

    const int lmOff = (lane & 15) * ASTRIDE + ((lane >> 4) & 1) * 4;

    float acc[4][4][4];
    #pragma unroll
    for (int i = 0; i < 4; i++)
        #pragma unroll
        for (int j = 0; j < 4; j++)
            #pragma unroll
            for (int q = 0; q < 4; q++) acc[i][j][q] = 0.f;

    auto issue = [&](int stage, int t) {
        int k0 = t * BKT;
        #pragma unroll
        for (int i = 0; i < 4; i++) {
            int v = tid + i * 256;
            int r = v >> 3, c = (v & 7) * 4;
            int gr = rowBase + r, gc = k0 + c;
            unsigned dst = aSm + (unsigned)(stage * BM * ASTRIDE + r * ASTRIDE + c) * 4;
            cp16(dst, p.A + (size_t)gr * p.lda + gc, (gr < p.M && gc < p.K) ? 16 : 0);
        }
        #pragma unroll
        for (int i = 0; i < 4; i++) {
            int v = tid + i * 256;
            int r = v >> 5, c = (v & 31) * 4;
            int gr = k0 + r, gc = colBase + c;
            unsigned dst = bBase + (unsigned)(stage * BKT * BSTRIDE + r * BSTRIDE + c) * 4;
            cp16(dst, p.B + (size_t)gr * p.N + gc, (gr < p.K && gc < p.N) ? 16 : 0);
        }
    };

    issue(0, 0);
    asm volatile("cp.async.commit_group;\n");

    for (int t = 0; t < ntiles; t++) {
        asm volatile("cp.async.wait_group 0;\n");
        __syncthreads();
        if (t + 1 < ntiles) issue((t + 1) & 1, t + 1);
        asm volatile("cp.async.commit_group;\n");
        int b = t & 1;
        const unsigned aStage = aSm + (unsigned)(b * BM * ASTRIDE) * 4;
        #pragma unroll
        for (int kk = 0; kk < BKT; kk += 8) {
            unsigned bf[4][2];
            #pragma unroll
            for (int nt = 0; nt < 4; nt++) {
                int n = wn * 32 + nt * 8 + grp;
                bf[nt][0] = __float_as_uint(Bs[b][kk + tig][n]);
                bf[nt][1] = __float_as_uint(Bs[b][kk + tig + 4][n]);
            }
            #pragma unroll
            for (int mt = 0; mt < 4; mt++) {
                unsigned aAddr = aStage +
                    (unsigned)(((wm * 64 + mt * 16) * ASTRIDE) + kk + lmOff) * 4;
                unsigned a0, a1, a2, a3;
                asm volatile(
                    "ldmatrix.sync.aligned.m8n8.x4.shared.b16 {%0,%1,%2,%3}, [%4];"
                    : "=r"(a0), "=r"(a1), "=r"(a2), "=r"(a3) : "r"(aAddr));
                #pragma unroll
                for (int nt = 0; nt < 4; nt++) {
                    asm volatile(
                        "mma.sync.aligned.m16n8k8.row.col.f32.tf32.tf32.f32 "
                        "{%0,%1,%2,%3}, {%4,%5,%6,%7}, {%8,%9}, {%0,%1,%2,%3};\n"
                        : "+f"(acc[mt][nt][0]), "+f"(acc[mt][nt][1]),
                          "+f"(acc[mt][nt][2]), "+f"(acc[mt][nt][3])
                        : "r"(a0), "r"(a1), "r"(a2), "r"(a3),
                          "r"(bf[nt][0]), "r"(bf[nt][1]));
                }
            }
        }
    }

    #pragma unroll
    for (int mt = 0; mt < 4; mt++) {
        #pragma unroll
        for (int nt = 0; nt < 4; nt++) {
            int r0 = rowBase + wm * 64 + mt * 16 + grp;
            int c0 = colBase + wn * 32 + nt * 8 + tig * 2;
            #pragma unroll
            for (int half = 0; half < 2; half++) {
                int r = r0 + half * 8;
                if (r >= p.M) continue;
                #pragma unroll
                for (int j = 0; j < 2; j++) {
                    int c = c0 + j;
                    if (c >= p.nstore) continue;
                    float v = acc[mt][nt][half * 2 + j];
                    if (p.bias) v += p.bias[c];
                    v *= p.scale;
                    if (p.leaky) v = leakyf(v);
                    if (p.rnd) v = rna(v);
                    p.C[(size_t)r * p.ldc + c] = v;
                    if (p.bfOut) p.bfOut[(size_t)r * H + c] = __float2bfloat16_rn(v);
                }
            }
        }
    }
}

__global__ __launch_bounds__(256, 2)
void mma_gemm_single(GP p)
{
    extern __shared__ float smemBuf[];
    gemm_body(p, blockIdx.x, blockIdx.y, smemBuf);
}

__global__ __launch_bounds__(256, 2)
void mma_gemm_dual(GP p0, GP p1, int gx0, int n0, int gx1)
{
    extern __shared__ float smemBuf[];
    int bid = blockIdx.x;
    if (bid < n0) gemm_body(p0, bid % gx0, bid / gx0, smemBuf);
    else {
        bid -= n0;
        gemm_body(p1, bid % gx1, bid / gx1, smemBuf);
    }
}

// ---------------------------- CSR build kernels ----------------------------
__global__ void hist_kernel(const int* __restrict__ dst, int* __restrict__ cnt, int n)
{
    int e = blockIdx.x * 256 + threadIdx.x;
    if (e < n) atomicAdd(&cnt[dst[e]], 1);
}

__global__ __launch_bounds__(1024)
void scan4_kernel(const int* __restrict__ cntAll, int* __restrict__ offw,
                  int* __restrict__ offe)
{
    int b = blockIdx.x;
    const int* cnt;
    int* off;
    int n;
    if (b < 3) { cnt = cntAll + b * NW; off = offw + b * (NW + 1); n = NW; }
    else       { cnt = cntAll + 3 * NW; off = offe; n = NE; }
    __shared__ int sm[1024];
    __shared__ int carry;
    if (threadIdx.x == 0) carry = 0;
    __syncthreads();
    for (int base = 0; base < n; base += 1024) {
        int i = base + threadIdx.x;
        int v = (i < n) ? cnt[i] : 0;
        sm[threadIdx.x] = v;
        __syncthreads();
        for (int o = 1; o < 1024; o <<= 1) {
            int t = (threadIdx.x >= o) ? sm[threadIdx.x - o] : 0;
            __syncthreads();
            sm[threadIdx.x] += t;
            __syncthreads();
        }
        if (i < n) off[i] = carry + sm[threadIdx.x] - v;
        __syncthreads();
        if (threadIdx.x == 1023) carry += sm[1023];
        __syncthreads();
    }
    if (threadIdx.x == 0) off[n] = carry;
}

__global__ void place_kernel(const int* __restrict__ src, const int* __restrict__ dst,
                             const int* __restrict__ ij, const int* __restrict__ off,
                             int* __restrict__ cur, int* __restrict__ psrc,
                             int* __restrict__ pij, int n)
{
    int e = blockIdx.x * 256 + threadIdx.x;
    if (e >= n) return;
    int d = dst[e];
    int p = off[d] + atomicAdd(&cur[d], 1);
    psrc[p] = src[e];
    if (pij) pij[p] = ij[e];
}

// --------- fused aggregation: blocks [0,3*NW) window, [3*NW, 3*NW+NE) edge ---------
__global__ __launch_bounds__(128)
void agg_all_kernel(const int* __restrict__ offw, const int* __restrict__ psrcw,
                    const int* __restrict__ pijw,
                    const int* __restrict__ offe, const int* __restrict__ psrce,
                    const __nv_bfloat16* __restrict__ hwbf,
                    const __nv_bfloat16* __restrict__ hebf,
                    float* __restrict__ wOut, float* __restrict__ eOut, int withEdge)
{
    int b = blockIdx.x;
    int c = threadIdx.x;
    float4 acc = make_float4(0.f, 0.f, 0.f, 0.f);

    if (b < NREL * NW) {
        int r = b / NW, d = b - r * NW;
        const int* off  = offw + r * (NW + 1);
        const int* psrc = psrcw + (size_t)r * ER;
        const int* pij  = pijw + (size_t)r * ER;
        int s0 = off[d], s1 = off[d + 1];
        int k = s0;
        for (; k + 1 < s1; k += 2) {
            int i0 = psrc[k], i1 = psrc[k + 1];
            int j0 = pij[k],  j1 = pij[k + 1];
            uint2 aw0 = *(const uint2*)(hwbf + (size_t)i0 * H + (c << 2));
            uint2 aw1 = *(const uint2*)(hwbf + (size_t)i1 * H + (c << 2));
            uint2 ae0 = *(const uint2*)(hebf + (size_t)j0 * H + (c << 2));
            uint2 ae1 = *(const uint2*)(hebf + (size_t)j1 * H + (c << 2));
            float2 p0 = __bfloat1622float2(*reinterpret_cast<__nv_bfloat162*>(&aw0.x));
            float2 p1 = __bfloat1622float2(*reinterpret_cast<__nv_bfloat162*>(&aw0.y));
            float2 q0 = __bfloat1622float2(*reinterpret_cast<__nv_bfloat162*>(&ae0.x));
            float2 q1 = __bfloat1622float2(*reinterpret_cast<__nv_bfloat162*>(&ae0.y));
            float2 p2 = __bfloat1622float2(*reinterpret_cast<__nv_bfloat162*>(&aw1.x));
            float2 p3 = __bfloat1622float2(*reinterpret_cast<__nv_bfloat162*>(&aw1.y));
            float2 q2 = __bfloat1622float2(*reinterpret_cast<__nv_bfloat162*>(&ae1.x));
            float2 q3 = __bfloat1622float2(*reinterpret_cast<__nv_bfloat162*>(&ae1.y));
            acc.x += (p0.x + q0.x) + (p2.x + q2.x);
            acc.y += (p0.y + q0.y) + (p2.y + q2.y);
            acc.z += (p1.x + q1.x) + (p3.x + q3.x);
            acc.w += (p1.y + q1.y) + (p3.y + q3.y);
        }
        if (k < s1) {
            uint2 aw = *(const uint2*)(hwbf + (size_t)psrc[k] * H + (c << 2));
            uint2 ae = *(const uint2*)(hebf + (size_t)pij[k] * H + (c << 2));
            float2 w0 = __bfloat1622float2(*reinterpret_cast<__nv_bfloat162*>(&aw.x));
            float2 w1 = __bfloat1622float2(*reinterpret_cast<__nv_bfloat162*>(&aw.y));
            float2 e0 = __bfloat1622float2(*reinterpret_cast<__nv_bfloat162*>(&ae.x));
            float2 e1 = __bfloat1622float2(*reinterpret_cast<__nv_bfloat162*>(&ae.y));
            acc.x += w0.x + e0.x; acc.y += w0.y + e0.y;
            acc.z += w1.x + e1.x; acc.w += w1.y + e1.y;
        }
        float rc = 1.f / fmaxf((float)(s1 - s0), 1.f);
        float4 o = make_float4(rna(acc.x * rc), rna(acc.y * rc),
                               rna(acc.z * rc), rna(acc.w * rc));
        *(float4*)(wOut + (size_t)d * WCAT + (size_t)(1 + r) * H + (c << 2)) = o;
    } else if (withEdge) {
        int d = b - NREL * NW;
        int s0 = offe[d], s1 = offe[d + 1];
        int k = s0;
        for (; k + 1 < s1; k += 2) {
            int i0 = psrce[k], i1 = psrce[k + 1];
            uint2 a0 = *(const uint2*)(hebf + (size_t)i0 * H + (c << 2));
            uint2 a1 = *(const uint2*)(hebf + (size_t)i1 * H + (c << 2));
            float2 e0 = __bfloat1622float2(*reinterpret_cast<__nv_bfloat162*>(&a0.x));
            float2 e1 = __bfloat1622float2(*reinterpret_cast<__nv_bfloat162*>(&a0.y));
            float2 f0 = __bfloat1622float2(*reinterpret_cast<__nv_bfloat162*>(&a1.x));
            float2 f1 = __bfloat1622float2(*reinterpret_cast<__nv_bfloat162*>(&a1.y));
            acc.x += e0.x + f0.x; acc.y += e0.y + f0.y;
            acc.z += e1.x + f1.x; acc.w += e1.y + f1.y;
        }
        if (k < s1) {
            uint2 a = *(const uint2*)(hebf + (size_t)psrce[k] * H + (c << 2));
            float2 e0 = __bfloat1622float2(*reinterpret_cast<__nv_bfloat162*>(&a.x));
            float2 e1 = __bfloat1622float2(*reinterpret_cast<__nv_bfloat162*>(&a.y));
            acc.x += e0.x; acc.y += e0.y; acc.z += e1.x; acc.w += e1.y;
        }
        float rc = 1.f / fmaxf((float)(s1 - s0), 1.f);
        float4 o = make_float4(rna(acc.x * rc), rna(acc.y * rc),
                               rna(acc.z * rc), rna(acc.w * rc));
        *(float4*)(eOut + (size_t)d * ECAT + (c << 2)) = o;
    }
}

// ---------------------------- pooling kernels ----------------------------
// all 4 layers' wfin = W1@(Wk@(S@Wq)) — pure function of weights; 4 blocks
__global__ __launch_bounds__(512)
void pool_head_all_kernel(const float* __restrict__ S, const float* __restrict__ Wq,
                          const float* __restrict__ Wk, const float* __restrict__ W1,
                          float* __restrict__ wfin_out)
{
    int l = blockIdx.x;
    size_t wOff = (size_t)l * H * H;
    const float* Sl  = S + (size_t)l * H;
    const float* Wql = Wq + wOff;
    const float* Wkl = Wk + wOff;
    const float* W1l = W1 + wOff;
    __shared__ float sS[H], sq[H], swk[H];
    int tid = threadIdx.x;
    sS[tid] = Sl[tid];
    __syncthreads();
    float acc = 0.f;
    for (int k = 0; k < H; k++) acc += sS[k] * Wql[(size_t)k * H + tid];
    sq[tid] = acc;
    __syncthreads();
    int warp = tid >> 5, lane = tid & 31;
    for (int row = warp; row < H; row += 16) {
        float a = 0.f;
        for (int j = lane; j < H; j += 32) a += Wkl[(size_t)row * H + j] * sq[j];
        #pragma unroll
        for (int o = 16; o > 0; o >>= 1) a += __shfl_down_sync(0xffffffffu, a, o);
        if (!lane) swk[row] = a;
    }
    __syncthreads();
    for (int row = warp; row < H; row += 16) {
        float a = 0.f;
        for (int j = lane; j < H; j += 32) a += W1l[(size_t)row * H + j] * swk[j];
        #pragma unroll
        for (int o = 16; o > 0; o >>= 1) a += __shfl_down_sync(0xffffffffu, a, o);
        if (!lane) wfin_out[l * H + row] = a;
    }
}

__global__ void scores_kernel(const __nv_bfloat16* __restrict__ hwbf,
                              const float* __restrict__ w, float* __restrict__ s,
                              float scale)
{
    int row = (blockIdx.x * blockDim.x + threadIdx.x) >> 5;
    int lane = threadIdx.x & 31;
    if (row >= NW) return;
    const __nv_bfloat16* p = hwbf + (size_t)row * H;
    float acc = 0.f;
    for (int c = lane; c < H; c += 32) acc += __bfloat162float(p[c]) * w[c];
    #pragma unroll
    for (int o = 16; o > 0; o >>= 1) acc += __shfl_down_sync(0xffffffffu, acc, o);
    if (!lane) s[row] = acc * scale;
}

__global__ __launch_bounds__(1024)
void softmax1b_kernel(float* __restrict__ s, int n, float* __restrict__ stat)
{
    __shared__ float red[32];
    int tid = threadIdx.x;
    float m = -3.4e38f;
    for (int i = tid; i < n; i += 1024) m = fmaxf(m, s[i]);
    #pragma unroll
    for (int o = 16; o > 0; o >>= 1) m = fmaxf(m, __shfl_down_sync(0xffffffffu, m, o));
    if ((tid & 31) == 0) red[tid >> 5] = m;
    __syncthreads();
    if (tid < 32) {
        float v = red[tid];
        #pragma unroll
        for (int o = 16; o > 0; o >>= 1) v = fmaxf(v, __shfl_down_sync(0xffffffffu, v, o));
        if (!tid) red[0] = v;
    }
    __syncthreads();
    float mx = red[0];
    __syncthreads();
    float sum = 0.f;
    for (int i = tid; i < n; i += 1024) {
        float e = expf(s[i] - mx);
        s[i] = e;
        sum += e;
    }
    #pragma unroll
    for (int o = 16; o > 0; o >>= 1) sum += __shfl_down_sync(0xffffffffu, sum, o);
    if ((tid & 31) == 0) red[tid >> 5] = sum;
    __syncthreads();
    if (tid < 32) {
        float v = red[tid];
        #pragma unroll
        for (int o = 16; o > 0; o >>= 1) v += __shfl_down_sync(0xffffffffu, v, o);
        if (!tid) { stat[0] = mx; stat[1] = v; }
    }
}

__global__ void attnv_kernel(const __nv_bfloat16* __restrict__ hwbf,
                             const float* __restrict__ w, const float* __restrict__ sum,
                             float* __restrict__ out, int n)
{
    int c = blockIdx.x * 256 + threadIdx.x;
    int chunk = (n + gridDim.y - 1) / gridDim.y;
    int r0 = blockIdx.y * chunk;
    int r1 = min(r0 + chunk, n);
    float acc = 0.f;
    for (int r = r0; r < r1; r++)
        acc += w[r] * __bfloat162float(hwbf[(size_t)r * H + c]);
    atomicAdd(&out[c], acc / sum[0]);
}

__global__ __launch_bounds__(512)
void pool_tail_kernel(const float* __restrict__ u, const float* __restrict__ W1,
                      const float* __restrict__ b1, const float* __restrict__ Wv,
                      const float* __restrict__ W2, const float* __restrict__ b2,
                      const float* __restrict__ Wg, const float* __restrict__ cb,
                      float* __restrict__ bs2)
{
    __shared__ float s0[H], s1[H], s2[H];
    int tid = threadIdx.x;
    s0[tid] = u[tid];
    __syncthreads();
    float acc = b1[tid];
    for (int k = 0; k < H; k++) acc += s0[k] * W1[(size_t)k * H + tid];
    s1[tid] = acc;
    __syncthreads();
    acc = 0.f;
    for (int k = 0; k < H; k++) acc += s1[k] * Wv[(size_t)k * H + tid];
    s2[tid] = acc;
    __syncthreads();
    acc = b2[tid];
    for (int k = 0; k < H; k++) acc += s2[k] * W2[(size_t)k * H + tid];
    s0[tid] = acc;
    __syncthreads();
    acc = 0.f;
    const float* Wg1 = Wg + (size_t)H * H;
    const float* Wg2 = Wg + 2 * (size_t)H * H;
    for (int k = 0; k < H; k++) {
        size_t o = (size_t)k * H + tid;
        acc += s0[k] * (Wg[o] + Wg1[o] + Wg2[o]);
    }
    bs2[tid] = acc + cb[tid] + cb[H + tid] + cb[2 * H + tid];
}

// ---------------------------- small kernels ----------------------------
__global__ void padx_kernel(const float* __restrict__ x, float* __restrict__ xp)
{
    size_t idx = (size_t)blockIdx.x * blockDim.x + threadIdx.x;
    if (idx >= (size_t)NE * ECHP) return;
    int r = (int)(idx / ECHP), c = (int)(idx % ECHP);
    xp[idx] = (c < ECH) ? rna(x[(size_t)r * ECH + c]) : 0.f;
}

__global__ void padw_kernel(const float* __restrict__ w, float* __restrict__ wp)
{
    size_t idx = (size_t)blockIdx.x * blockDim.x + threadIdx.x;
    if (idx >= (size_t)ECHP * H) return;
    int r = (int)(idx / H);
    wp[idx] = (r < ECH) ? rna(w[idx]) : 0.f;
}

__global__ void padlin_kernel(const float* __restrict__ w, float* __restrict__ wp)
{
    int idx = blockIdx.x * 256 + threadIdx.x;
    if (idx >= H * 256) return;
    int r = idx >> 8, c = idx & 255;
    wp[idx] = (c < OUT_DIM) ? rna(w[r * OUT_DIM + c]) : 0.f;
}

__global__ void rcopy_kernel(const float* __restrict__ in, float* __restrict__ out, size_t n)
{
    size_t idx = (size_t)blockIdx.x * blockDim.x + threadIdx.x;
    if (idx < n) out[idx] = rna(in[idx]);
}

__global__ void build_bw_kernel(const float* __restrict__ Wl, const float* __restrict__ Wr,
                                float* __restrict__ out)
{
    size_t idx = (size_t)blockIdx.x * blockDim.x + threadIdx.x;
    if (idx >= (size_t)WCAT * H) return;
    int row = (int)(idx / H), j = (int)(idx % H);
    float v;
    if (row < H) {
        v = Wr[(size_t)row * H + j] + Wr[(size_t)(H + row) * H + j]
          + Wr[(size_t)(2 * H + row) * H + j];
    } else {
        v = Wl[(size_t)(row - H) * H + j];
    }
    out[idx] = rna(v);
}

__global__ void build_be_kernel(const float* __restrict__ Wl, const float* __restrict__ Wr,
                                float* __restrict__ out)
{
    size_t idx = (size_t)blockIdx.x * blockDim.x + threadIdx.x;
    if (idx >= (size_t)ECAT * H) return;
    int row = (int)(idx / H), j = (int)(idx % H);
    out[idx] = rna((row < H) ? Wr[(size_t)row * H + j] : Wl[(size_t)(row - H) * H + j]);
}

// ------------------------------- host orchestration -------------------------------
static GP mkGP(const float* A, const float* B, float* C, int M, int N, int K,
               int lda, int ldc, int nstore, const float* bias, float scale,
               int leaky, int rnd, __nv_bfloat16* bfOut)
{
    GP p; p.A = A; p.B = B; p.C = C; p.M = M; p.N = N; p.K = K;
    p.lda = lda; p.ldc = ldc; p.nstore = nstore; p.bias = bias;
    p.scale = scale; p.leaky = leaky; p.rnd = rnd; p.bfOut = bfOut;
    return p;
}

static void gemmSingle(const GP& p)
{
    dim3 grid((p.N + BN - 1) / BN, (p.M + BM - 1) / BM);
    mma_gemm_single<<<grid, 256, GEMM_SMEM>>>(p);
}

static void gemmDual(const GP& a, const GP& b)
{
    int gxa = (a.N + BN - 1) / BN, gya = (a.M + BM - 1) / BM;
    int gxb = (b.N + BN - 1) / BN, gyb = (b.M + BM - 1) / BM;
    int n0 = gxa * gya;
    mma_gemm_dual<<<n0 + gxb * gyb, 256, GEMM_SMEM>>>(a, b, gxa, n0, gxb);
}

extern "C" void kernel_launch(void* const* d_in, const int* in_sizes, int n_in,
                              void* d_out, int out_size)
{
    const float* x_win       = (const float*)d_in[0];
    const float* x_edge      = (const float*)d_in[1];
    const float* W_pre_win   = (const float*)d_in[2];
    const float* W_post_win  = (const float*)d_in[3];
    const float* W_pre_edge  = (const float*)d_in[4];
    const float* W_post_edge = (const float*)d_in[5];
    const float* conv_Wl     = (const float*)d_in[6];
    const float* conv_Wr     = (const float*)d_in[7];
    const float* conv_Wg     = (const float*)d_in[8];
    const float* conv_b      = (const float*)d_in[9];
    const float* econv_Wl    = (const float*)d_in[10];
    const float* econv_Wr    = (const float*)d_in[11];
    const float* econv_b     = (const float*)d_in[12];
    const float* pool_lin1_W = (const float*)d_in[13];
    const float* pool_lin1_b = (const float*)d_in[14];
    const float* pool_S      = (const float*)d_in[15];
    const float* pool_Wq     = (const float*)d_in[16];
    const float* pool_Wk     = (const float*)d_in[17];
    const float* pool_Wv     = (const float*)d_in[18];
    const float* pool_lin2_W = (const float*)d_in[19];
    const float* pool_lin2_b = (const float*)d_in[20];
    const float* lin_W       = (const float*)d_in[21];
    const float* lin_b       = (const float*)d_in[22];
    const int* ein = (const int*)d_in[23];
    const int* eic = (const int*)d_in[24];
    const int* eis = (const int*)d_in[25];
    const int* ijn = (const int*)d_in[26];
    const int* ijc = (const int*)d_in[27];
    const int* ijs = (const int*)d_in[28];
    const int* eee = (const int*)d_in[29];

    static int smemSet = 0;
    if (!smemSet) {
        cudaFuncSetAttribute(mma_gemm_single, cudaFuncAttributeMaxDynamicSharedMemorySize,
                             GEMM_SMEM);
        cudaFuncSetAttribute(mma_gemm_dual, cudaFuncAttributeMaxDynamicSharedMemorySize,
                             GEMM_SMEM);
        smemSet = 1;
    }

    float *wcatA, *wcatB, *ecatA, *ecatB, *xpad, *wpad, *tmp, *tmp2, *Bw, *Be, *lpad;
    float *sbuf, *stat, *wfinA, *vec;
    __nv_bfloat16 *hwbf, *hebf;
    int *cnt4, *cur4, *offw, *offe, *psrcw, *pijw, *psrce;
    cudaGetSymbolAddress((void**)&wcatA, g_wcatA);
    cudaGetSymbolAddress((void**)&wcatB, g_wcatB);
    cudaGetSymbolAddress((void**)&ecatA, g_ecatA);
    cudaGetSymbolAddress((void**)&ecatB, g_ecatB);
    cudaGetSymbolAddress((void**)&hwbf,  g_hwbf);
    cudaGetSymbolAddress((void**)&hebf,  g_hebf);
    cudaGetSymbolAddress((void**)&xpad,  g_xpad);
    cudaGetSymbolAddress((void**)&wpad,  g_wpad);
    cudaGetSymbolAddress((void**)&tmp,   g_tmp);
    cudaGetSymbolAddress((void**)&tmp2,  g_tmp2);
    cudaGetSymbolAddress((void**)&Bw,    g_Bw);
    cudaGetSymbolAddress((void**)&Be,    g_Be);
    cudaGetSymbolAddress((void**)&lpad,  g_lpad);
    cudaGetSymbolAddress((void**)&sbuf,  g_s);
    cudaGetSymbolAddress((void**)&stat,  g_stat);
    cudaGetSymbolAddress((void**)&wfinA, g_wfin);
    cudaGetSymbolAddress((void**)&vec,   g_vec);
    cudaGetSymbolAddress((void**)&cnt4,  g_cnt4);
    cudaGetSymbolAddress((void**)&cur4,  g_cur4);
    cudaGetSymbolAddress((void**)&offw,  g_offw);
    cudaGetSymbolAddress((void**)&offe,  g_offe);
    cudaGetSymbolAddress((void**)&psrcw, g_psrcw);
    cudaGetSymbolAddress((void**)&pijw,  g_pijw);
    cudaGetSymbolAddress((void**)&psrce, g_psrce);

    float* u   = vec + H;
    float* bs2 = vec + 2 * H;

    const int* srcs[NREL] = {ein, eic, eis};
    const int* ijx[NREL]  = {ijn, ijc, ijs};

    // ---- CSR build: batched ----
    cudaMemsetAsync(cnt4, 0, (3 * NW + NE) * sizeof(int));
    cudaMemsetAsync(cur4, 0, (3 * NW + NE) * sizeof(int));
    for (int r = 0; r < NREL; r++)
        hist_kernel<<<(ER + 255) / 256, 256>>>(srcs[r] + ER, cnt4 + r * NW, ER);
    hist_kernel<<<(EE + 255) / 256, 256>>>(eee + EE, cnt4 + 3 * NW, EE);
    scan4_kernel<<<4, 1024>>>(cnt4, offw, offe);
    for (int r = 0; r < NREL; r++)
        place_kernel<<<(ER + 255) / 256, 256>>>(srcs[r], srcs[r] + ER, ijx[r],
                                                offw + r * (NW + 1), cur4 + r * NW,
                                                psrcw + (size_t)r * ER,
                                                pijw + (size_t)r * ER, ER);
    place_kernel<<<(EE + 255) / 256, 256>>>(eee, eee + EE, nullptr, offe, cur4 + 3 * NW,
                                            psrce, nullptr, EE);

    // ---- rounded operand staging + hoisted pool heads ----
    padx_kernel<<<(int)(((size_t)NE * ECHP + 255) / 256), 256>>>(x_edge, xpad);
    padw_kernel<<<(int)(((size_t)ECHP * H + 255) / 256), 256>>>(W_pre_edge, wpad);
    rcopy_kernel<<<(int)(((size_t)NW * MDIM + 255) / 256), 256>>>(
        x_win, wcatB, (size_t)NW * MDIM);
    rcopy_kernel<<<(H * H + 255) / 256, 256>>>(W_pre_win, Bw, (size_t)H * H);
    rcopy_kernel<<<(H * H + 255) / 256, 256>>>(W_post_win, Bw + (size_t)H * H, (size_t)H * H);
    rcopy_kernel<<<(H * H + 255) / 256, 256>>>(W_post_edge, Be, (size_t)H * H);
    pool_head_all_kernel<<<NLAYER, 512>>>(pool_S, pool_Wq, pool_Wk, pool_lin1_W, wfinA);

    // ---- pretransforms: dual-problem launches (window ‖ edge) ----
    gemmDual(mkGP(wcatB, Bw, tmp2, NW, H, MDIM, MDIM, H, H, nullptr, 1.f, 1, 1, nullptr),
             mkGP(xpad, wpad, tmp, NE, H, ECHP, ECHP, H, H, nullptr, 1.f, 1, 1, nullptr));
    gemmDual(mkGP(tmp2, Bw + (size_t)H * H, wcatA, NW, H, H, H, WCAT, H,
                  nullptr, 1.f, 1, 1, hwbf),
             mkGP(tmp, Be, ecatA, NE, H, H, H, ECAT, H, nullptr, 1.f, 1, 1, hebf));

    float* wA = wcatA; float* wB = wcatB;
    float* eA = ecatA; float* eB = ecatB;
    const float scale = 1.f / sqrtf((float)H);

    for (int l = 0; l < NLAYER; l++) {
        size_t wOff = (size_t)l * H * H;
        size_t wb   = (size_t)l * NREL * H * H;
        size_t bb   = (size_t)l * NREL * H;
        int withEdge = (l < NLAYER - 1) ? 1 : 0;

        // ---- pooling (wfin precomputed) ----
        scores_kernel<<<(NW * 32 + 255) / 256, 256>>>(hwbf, wfinA + l * H, sbuf, scale);
        softmax1b_kernel<<<1, 1024>>>(sbuf, NW, stat);
        cudaMemsetAsync(u, 0, H * sizeof(float));
        {
            dim3 ag(H / 256, 79);
            attnv_kernel<<<ag, 256>>>(hwbf, sbuf, stat + 1, u, NW);
        }
        pool_tail_kernel<<<1, 512>>>(u, pool_lin1_W + wOff, pool_lin1_b + (size_t)l * H,
                                     pool_Wv + wOff, pool_lin2_W + wOff,
                                     pool_lin2_b + (size_t)l * H,
                                     conv_Wg + wb, conv_b + bb, bs2);
        build_bw_kernel<<<(int)(((size_t)WCAT * H + 255) / 256), 256>>>(
            conv_Wl + wb, conv_Wr + wb, Bw);
        if (withEdge)
            build_be_kernel<<<(int)(((size_t)ECAT * H + 255) / 256), 256>>>(
                econv_Wl + wOff, econv_Wr + wOff, Be);

        // ---- fused aggregation (window relations + edge graph, one launch) ----
        agg_all_kernel<<<NREL * NW + (withEdge ? NE : 0), 128>>>(
            offw, psrcw, pijw, offe, psrce, hwbf, hebf, wA, eA + H, withEdge);

        // ---- conv GEMMs ----
        GP wp = mkGP(wA, Bw, wB, NW, H, WCAT, WCAT, WCAT, H,
                     bs2, 1.f / (float)NREL, 1, 1, hwbf);
        if (withEdge) {
            GP ep = mkGP(eA, Be, eB, NE, H, ECAT, ECAT, ECAT, H,
                         econv_b + (size_t)l * H, 1.f, 1, 1, hebf);
            gemmDual(wp, ep);
        } else {
            gemmSingle(wp);
        }

        float* t = wA; wA = wB; wB = t;
        t = eA; eA = eB; eB = t;
    }

    // ---- final linear on the aligned path (lin_W padded into lpad) ----
    padlin_kernel<<<(H * 256 + 255) / 256, 256>>>(lin_W, lpad);
    gemmSingle(mkGP(wA, lpad, (float*)d_out, NW, 256, H, WCAT, OUT_DIM, OUT_DIM,
                    lin_b, 1.f, 0, 0, nullptr));
}